// round 3
// baseline (speedup 1.0000x reference)
#include <cuda_runtime.h>
#include <cuda_bf16.h>
#include <math.h>

// Problem constants
#define NN 64    // batch n
#define CC 256   // channels c
#define SS 64    // seq s
#define PP 16    // parts p
#define KK 4     // clusters k
#define NH 4     // heads
#define HD 64    // head dim
#define NB (NN*PP)   // 1024 attention batches

// Scratch (no cudaMalloc allowed)
__device__ float g_xt[NB*SS*CC];        // (n,p,s,c) == (b,s,c)   64 MB
__device__ float g_xattn[NB*SS*CC];     // attention out + residual, 64 MB
__device__ float g_protn[PP*KK*CC];     // normalized prototypes
__device__ float g_clustered[PP*NN*KK*CC];
__device__ unsigned char g_idx[PP*NN*SS];

// ---------------------------------------------------------------------------
// Kernel 0: transpose x (n,c,s,p) -> g_xt (n,p,s,c)
// ---------------------------------------------------------------------------
__global__ void transpose_kernel(const float* __restrict__ x) {
    __shared__ float tile[256*17];
    int bx = blockIdx.x;          // n*64 + s
    int n = bx >> 6, s = bx & 63;
    int t = threadIdx.x;
    const float* src = x + (size_t)n*262144 + (size_t)s*16;
    #pragma unroll
    for (int w = 0; w < 16; w++) {
        int i = t + w*256;
        int c = i >> 4, pp = i & 15;
        tile[c*17 + pp] = src[(size_t)c*1024 + pp];
    }
    __syncthreads();
    float* dst = g_xt + (size_t)n*262144 + (size_t)s*256;
    #pragma unroll
    for (int w = 0; w < 16; w++) {
        dst[(size_t)w*16384 + t] = tile[t*17 + w];   // p=w, c=t
    }
}

// ---------------------------------------------------------------------------
// Kernel 1: normalize prototypes (p,k,c) over c
// ---------------------------------------------------------------------------
__global__ void protonorm_kernel(const float* __restrict__ prot) {
    int r = blockIdx.x;          // p*4 + k  (64 rows)
    int t = threadIdx.x;         // 256
    float v = prot[r*256 + t];
    double sq = (double)v * (double)v;
    #pragma unroll
    for (int off = 16; off > 0; off >>= 1)
        sq += __shfl_down_sync(0xffffffffu, sq, off);
    __shared__ double red[8];
    if ((t & 31) == 0) red[t >> 5] = sq;
    __syncthreads();
    __shared__ float rn;
    if (t == 0) {
        double sum = 0.0;
        #pragma unroll
        for (int i = 0; i < 8; i++) sum += red[i];
        rn = (float)(1.0 / sqrt(sum));
    }
    __syncthreads();
    g_protn[r*256 + t] = v * rn;
}

// ---------------------------------------------------------------------------
// Kernel 2: instance-norm + cosine sim + argmax -> hard idx  (one block per (p,n))
// smem: X[64][256] + P[4][256] + mu[256] + rstd[256] = 71680 B
// ---------------------------------------------------------------------------
__global__ __launch_bounds__(256) void assign_kernel() {
    int p = blockIdx.x, n = blockIdx.y;
    extern __shared__ float sm[];
    float* Xs = sm;              // 16384
    float* P  = Xs + 16384;      // 1024
    float* MU = P + 1024;        // 256
    float* RS = MU + 256;        // 256
    int t = threadIdx.x;
    const float* src = g_xt + (size_t)(n*16 + p) * 16384;
    for (int i = t; i < 16384; i += 256) Xs[i] = src[i];
    const float* psrc = g_protn + p*1024;
    for (int i = t; i < 1024; i += 256) P[i] = psrc[i];
    __syncthreads();

    // per-channel mean/var over s (thread t = channel)
    {
        double s1 = 0.0, s2 = 0.0;
        #pragma unroll 8
        for (int s = 0; s < 64; s++) {
            double v = (double)Xs[s*256 + t];
            s1 += v; s2 += v*v;
        }
        double mu = s1 / 64.0;
        double var = s2 / 64.0 - mu*mu;
        MU[t] = (float)mu;
        RS[t] = (float)(1.0 / sqrt(var + 1e-5));
    }
    __syncthreads();

    int w = t >> 5, lane = t & 31;
    for (int it = 0; it < 8; it++) {
        int s = w*8 + it;
        double nrm = 0.0, d0 = 0.0, d1 = 0.0, d2 = 0.0, d3 = 0.0;
        #pragma unroll
        for (int cc = 0; cc < 8; cc++) {
            int c = lane + 32*cc;
            float yf = (Xs[s*256 + c] - MU[c]) * RS[c];
            double y = (double)yf;
            nrm += y*y;
            d0 += y * (double)P[c];
            d1 += y * (double)P[256 + c];
            d2 += y * (double)P[512 + c];
            d3 += y * (double)P[768 + c];
        }
        #pragma unroll
        for (int off = 16; off > 0; off >>= 1) {
            nrm += __shfl_down_sync(0xffffffffu, nrm, off);
            d0  += __shfl_down_sync(0xffffffffu, d0, off);
            d1  += __shfl_down_sync(0xffffffffu, d1, off);
            d2  += __shfl_down_sync(0xffffffffu, d2, off);
            d3  += __shfl_down_sync(0xffffffffu, d3, off);
        }
        if (lane == 0) {
            double rn = 1.0 / sqrt(nrm);
            double sv0 = d0*rn, sv1 = d1*rn, sv2 = d2*rn, sv3 = d3*rn;
            int best = 0; double bv = sv0;
            if (sv1 > bv) { bv = sv1; best = 1; }
            if (sv2 > bv) { bv = sv2; best = 2; }
            if (sv3 > bv) { bv = sv3; best = 3; }
            g_idx[(p*64 + n)*64 + s] = (unsigned char)best;
        }
    }
}

// ---------------------------------------------------------------------------
// Kernel 3: mode over parts -> cluster_indices (written as float)
// ---------------------------------------------------------------------------
__global__ void mode_kernel(float* __restrict__ outci) {
    int id = blockIdx.x*256 + threadIdx.x;
    if (id >= NN*SS) return;
    int n = id >> 6, s = id & 63;
    int c0 = 0, c1 = 0, c2 = 0, c3 = 0;
    #pragma unroll
    for (int p = 0; p < 16; p++) {
        int a = g_idx[(p*64 + n)*64 + s];
        c0 += (a == 0); c1 += (a == 1); c2 += (a == 2); c3 += (a == 3);
    }
    int best = 0, bc = c0;
    if (c1 > bc) { bc = c1; best = 1; }
    if (c2 > bc) { bc = c2; best = 2; }
    if (c3 > bc) { bc = c3; best = 3; }
    outci[id] = (float)best;
}

// ---------------------------------------------------------------------------
// Kernel 4: fused causal MHA + residual, one block per batch b
// smem: X[64][257] + O[64][257] + Q/K/V/S[64][65] = 198144 B
// ---------------------------------------------------------------------------
#define XST 257
#define QST 65
__global__ __launch_bounds__(256, 1) void attn_kernel(
    const float* __restrict__ Wq, const float* __restrict__ bq,
    const float* __restrict__ Wk, const float* __restrict__ bk,
    const float* __restrict__ Wv, const float* __restrict__ bv,
    const float* __restrict__ Wo, const float* __restrict__ bo) {
    extern __shared__ float sm[];
    float* Xs = sm;                    // 64*257
    float* Os = Xs + 64*XST;           // 64*257
    float* Qs = Os + 64*XST;           // 64*65
    float* Ks = Qs + 64*QST;
    float* Vs = Ks + 64*QST;
    float* Ss = Vs + 64*QST;
    int t = threadIdx.x;
    size_t b = blockIdx.x;
    const float* src = g_xt + b*16384;
    for (int i = t; i < 16384; i += 256)
        Xs[(i >> 8)*XST + (i & 255)] = src[i];
    __syncthreads();

    int j0 = t & 15, r0 = t >> 4;      // 16x16 thread tile, each does 4x4 outputs

    for (int h = 0; h < 4; h++) {
        // ---- Q, K, V projections for this head (64x256 @ 256x64 each) ----
        const float* Ws3[3] = { Wq, Wk, Wv };
        const float* Bs3[3] = { bq, bk, bv };
        float* Ds3[3] = { Qs, Ks, Vs };
        #pragma unroll
        for (int m = 0; m < 3; m++) {
            const float* W = Ws3[m] + h*64 + j0;
            float acc[4][4];
            #pragma unroll
            for (int a = 0; a < 4; a++)
                #pragma unroll
                for (int bb = 0; bb < 4; bb++) acc[a][bb] = 0.f;
            for (int i = 0; i < 256; i++) {
                float xv[4], wv[4];
                #pragma unroll
                for (int a = 0; a < 4; a++) xv[a] = Xs[(r0 + 16*a)*XST + i];
                #pragma unroll
                for (int bb = 0; bb < 4; bb++) wv[bb] = W[i*256 + 16*bb];
                #pragma unroll
                for (int a = 0; a < 4; a++)
                    #pragma unroll
                    for (int bb = 0; bb < 4; bb++)
                        acc[a][bb] = fmaf(xv[a], wv[bb], acc[a][bb]);
            }
            const float* bias = Bs3[m] + h*64 + j0;
            float* D = Ds3[m];
            #pragma unroll
            for (int a = 0; a < 4; a++)
                #pragma unroll
                for (int bb = 0; bb < 4; bb++)
                    D[(r0 + 16*a)*QST + j0 + 16*bb] = acc[a][bb] + bias[16*bb];
        }
        __syncthreads();

        // ---- scores S = Q K^T * 0.125 ----
        {
            float acc[4][4];
            #pragma unroll
            for (int a = 0; a < 4; a++)
                #pragma unroll
                for (int bb = 0; bb < 4; bb++) acc[a][bb] = 0.f;
            for (int d = 0; d < 64; d++) {
                float qv[4], kv[4];
                #pragma unroll
                for (int a = 0; a < 4; a++) qv[a] = Qs[(r0 + 16*a)*QST + d];
                #pragma unroll
                for (int bb = 0; bb < 4; bb++) kv[bb] = Ks[(j0 + 16*bb)*QST + d];
                #pragma unroll
                for (int a = 0; a < 4; a++)
                    #pragma unroll
                    for (int bb = 0; bb < 4; bb++)
                        acc[a][bb] = fmaf(qv[a], kv[bb], acc[a][bb]);
            }
            #pragma unroll
            for (int a = 0; a < 4; a++)
                #pragma unroll
                for (int bb = 0; bb < 4; bb++)
                    Ss[(r0 + 16*a)*QST + j0 + 16*bb] = acc[a][bb] * 0.125f;
        }
        __syncthreads();

        // ---- causal softmax, one thread per row ----
        if (t < 64) {
            int row = t;
            float m = -3.402823466e38f;
            for (int j = 0; j <= row; j++) m = fmaxf(m, Ss[row*QST + j]);
            float ssum = 0.f;
            for (int j = 0; j <= row; j++) {
                float e = expf(Ss[row*QST + j] - m);
                Ss[row*QST + j] = e;
                ssum += e;
            }
            float inv = 1.f / ssum;
            for (int j = 0; j <= row; j++) Ss[row*QST + j] *= inv;
            for (int j = row + 1; j < 64; j++) Ss[row*QST + j] = 0.f;
        }
        __syncthreads();

        // ---- head out = S @ V, written into concat columns of Os ----
        {
            float acc[4][4];
            #pragma unroll
            for (int a = 0; a < 4; a++)
                #pragma unroll
                for (int bb = 0; bb < 4; bb++) acc[a][bb] = 0.f;
            for (int j = 0; j < 64; j++) {
                float sv[4], vv[4];
                #pragma unroll
                for (int a = 0; a < 4; a++) sv[a] = Ss[(r0 + 16*a)*QST + j];
                #pragma unroll
                for (int bb = 0; bb < 4; bb++) vv[bb] = Vs[j*QST + j0 + 16*bb];
                #pragma unroll
                for (int a = 0; a < 4; a++)
                    #pragma unroll
                    for (int bb = 0; bb < 4; bb++)
                        acc[a][bb] = fmaf(sv[a], vv[bb], acc[a][bb]);
            }
            #pragma unroll
            for (int a = 0; a < 4; a++)
                #pragma unroll
                for (int bb = 0; bb < 4; bb++)
                    Os[(r0 + 16*a)*XST + h*64 + j0 + 16*bb] = acc[a][bb];
        }
        __syncthreads();
    }

    // ---- final: out = Os @ Wo + bo + X  -> g_xattn ----
    {
        int tc = t & 31, tr = t >> 5;     // warp-uniform row base
        float acc[8][8];
        #pragma unroll
        for (int a = 0; a < 8; a++)
            #pragma unroll
            for (int bb = 0; bb < 8; bb++) acc[a][bb] = 0.f;
        for (int i = 0; i < 256; i++) {
            float ov[8], wv[8];
            #pragma unroll
            for (int a = 0; a < 8; a++) ov[a] = Os[(tr + 8*a)*XST + i];
            #pragma unroll
            for (int bb = 0; bb < 8; bb++) wv[bb] = Wo[i*256 + tc + 32*bb];
            #pragma unroll
            for (int a = 0; a < 8; a++)
                #pragma unroll
                for (int bb = 0; bb < 8; bb++)
                    acc[a][bb] = fmaf(ov[a], wv[bb], acc[a][bb]);
        }
        float* dst = g_xattn + b*16384;
        #pragma unroll
        for (int a = 0; a < 8; a++) {
            int r = tr + 8*a;
            #pragma unroll
            for (int bb = 0; bb < 8; bb++) {
                int cj = tc + 32*bb;
                dst[r*256 + cj] = acc[a][bb] + bo[cj] + Xs[r*XST + cj];
            }
        }
    }
}

// ---------------------------------------------------------------------------
// Kernel 5: scatter-max pooling (one-hot assignment semantics, max includes 0
// whenever at least one timestep is assigned to a different cluster)
// ---------------------------------------------------------------------------
__global__ __launch_bounds__(256) void scatter_kernel() {
    int p = blockIdx.x, n = blockIdx.y, t = threadIdx.x;
    __shared__ unsigned char ids[64];
    if (t < 64) ids[t] = g_idx[(p*64 + n)*64 + t];
    __syncthreads();
    int c0 = 0, c1 = 0, c2 = 0, c3 = 0;
    #pragma unroll 8
    for (int s = 0; s < 64; s++) {
        int a = ids[s];
        c0 += (a == 0); c1 += (a == 1); c2 += (a == 2); c3 += (a == 3);
    }
    const float* src = g_xattn + (size_t)(n*16 + p)*16384 + t;
    float m0 = -3.402823466e38f, m1 = m0, m2 = m0, m3 = m0;
    #pragma unroll 8
    for (int s = 0; s < 64; s++) {
        float v = src[s*256];
        int a = ids[s];
        if (a == 0) m0 = fmaxf(m0, v);
        else if (a == 1) m1 = fmaxf(m1, v);
        else if (a == 2) m2 = fmaxf(m2, v);
        else m3 = fmaxf(m3, v);
    }
    if (c0 < 64) m0 = fmaxf(m0, 0.f);
    if (c1 < 64) m1 = fmaxf(m1, 0.f);
    if (c2 < 64) m2 = fmaxf(m2, 0.f);
    if (c3 < 64) m3 = fmaxf(m3, 0.f);
    float* dst = g_clustered + (size_t)(p*64 + n)*1024 + t;
    dst[0]   = m0;
    dst[256] = m1;
    dst[512] = m2;
    dst[768] = m3;
}

// ---------------------------------------------------------------------------
// Kernel 6: per-part FC: out[n,o,p] = sum_kc clustered[p,n,kc] * fc_bin[p,kc,o]
// grid (p, n-tile of 16), smem 64 KB input tile
// ---------------------------------------------------------------------------
__global__ __launch_bounds__(256) void fc_kernel(const float* __restrict__ fcb,
                                                 float* __restrict__ out) {
    int p = blockIdx.x, n0 = blockIdx.y * 16, t = threadIdx.x;
    extern __shared__ float cl[];   // [16][1024]
    for (int nn = 0; nn < 16; nn++) {
        const float* src = g_clustered + (size_t)(p*64 + n0 + nn)*1024;
        for (int i = t; i < 1024; i += 256) cl[nn*1024 + i] = src[i];
    }
    __syncthreads();
    int o0 = t & 63, g = t >> 6;    // g in 0..3 -> rows g*4..g*4+3
    float acc[4][4];
    #pragma unroll
    for (int a = 0; a < 4; a++)
        #pragma unroll
        for (int bb = 0; bb < 4; bb++) acc[a][bb] = 0.f;
    const float* F = fcb + (size_t)p*1024*256 + o0;
    for (int kc = 0; kc < 1024; kc++) {
        float wv[4], cv[4];
        #pragma unroll
        for (int bb = 0; bb < 4; bb++) wv[bb] = F[(size_t)kc*256 + 64*bb];
        #pragma unroll
        for (int a = 0; a < 4; a++) cv[a] = cl[(g*4 + a)*1024 + kc];
        #pragma unroll
        for (int a = 0; a < 4; a++)
            #pragma unroll
            for (int bb = 0; bb < 4; bb++)
                acc[a][bb] = fmaf(cv[a], wv[bb], acc[a][bb]);
    }
    #pragma unroll
    for (int a = 0; a < 4; a++) {
        int n = n0 + g*4 + a;
        #pragma unroll
        for (int bb = 0; bb < 4; bb++) {
            int o = o0 + 64*bb;
            out[(size_t)n*4096 + o*16 + p] = acc[a][bb];
        }
    }
}

// ---------------------------------------------------------------------------
extern "C" void kernel_launch(void* const* d_in, const int* in_sizes, int n_in,
                              void* d_out, int out_size) {
    const float* x    = (const float*)d_in[0];
    const float* prot = (const float*)d_in[1];
    const float* Wq   = (const float*)d_in[2];
    const float* bq   = (const float*)d_in[3];
    const float* Wk   = (const float*)d_in[4];
    const float* bk   = (const float*)d_in[5];
    const float* Wv   = (const float*)d_in[6];
    const float* bv   = (const float*)d_in[7];
    const float* Wo   = (const float*)d_in[8];
    const float* bo   = (const float*)d_in[9];
    const float* fcb  = (const float*)d_in[10];
    float* out = (float*)d_out;

    cudaFuncSetAttribute(attn_kernel, cudaFuncAttributeMaxDynamicSharedMemorySize, 198144);
    cudaFuncSetAttribute(assign_kernel, cudaFuncAttributeMaxDynamicSharedMemorySize, 71680);
    cudaFuncSetAttribute(fc_kernel, cudaFuncAttributeMaxDynamicSharedMemorySize, 65536);

    transpose_kernel<<<NN*SS, 256>>>(x);
    protonorm_kernel<<<PP*KK, 256>>>(prot);
    assign_kernel<<<dim3(PP, NN), 256, 71680>>>();
    if (out_size >= NN*CC*PP + NN*SS)
        mode_kernel<<<16, 256>>>(out + NN*CC*PP);
    attn_kernel<<<NB, 256, 198144>>>(Wq, bq, Wk, bk, Wv, bv, Wo, bo);
    scatter_kernel<<<dim3(PP, NN), 256>>>();
    fc_kernel<<<dim3(PP, 4), 256, 65536>>>(fcb, out);
}

// round 5
// speedup vs baseline: 1.1838x; 1.1838x over previous
#include <cuda_runtime.h>
#include <cuda_bf16.h>
#include <math.h>

// Problem constants
#define NN 64    // batch n
#define CC 256   // channels c
#define SS 64    // seq s
#define PP 16    // parts p
#define KK 4     // clusters k
#define NB (NN*PP)   // 1024 attention batches

// Scratch (no cudaMalloc allowed)
__device__ float g_xt[NB*SS*CC];        // (n,p,s,c) == (b,s,c)
__device__ float g_xattn[NB*SS*CC];     // attention out + residual
__device__ float g_protn[PP*KK*CC];
__device__ float g_clustered[PP*NN*KK*CC];
__device__ unsigned char g_idx[PP*NN*SS];

// ---------------------------------------------------------------------------
// Kernel 0: transpose x (n,c,s,p) -> g_xt (n,p,s,c)
// ---------------------------------------------------------------------------
__global__ void transpose_kernel(const float* __restrict__ x) {
    __shared__ float tile[256*17];
    int bx = blockIdx.x;          // n*64 + s
    int n = bx >> 6, s = bx & 63;
    int t = threadIdx.x;
    const float* src = x + (size_t)n*262144 + (size_t)s*16;
    #pragma unroll
    for (int w = 0; w < 16; w++) {
        int i = t + w*256;
        int c = i >> 4, pp = i & 15;
        tile[c*17 + pp] = src[(size_t)c*1024 + pp];
    }
    __syncthreads();
    float* dst = g_xt + (size_t)n*262144 + (size_t)s*256;
    #pragma unroll
    for (int w = 0; w < 16; w++) {
        dst[(size_t)w*16384 + t] = tile[t*17 + w];   // p=w, c=t
    }
}

// ---------------------------------------------------------------------------
// Kernel 1: normalize prototypes (p,k,c) over c
// ---------------------------------------------------------------------------
__global__ void protonorm_kernel(const float* __restrict__ prot) {
    int r = blockIdx.x;          // p*4 + k
    int t = threadIdx.x;         // 256
    float v = prot[r*256 + t];
    double sq = (double)v * (double)v;
    #pragma unroll
    for (int off = 16; off > 0; off >>= 1)
        sq += __shfl_down_sync(0xffffffffu, sq, off);
    __shared__ double red[8];
    if ((t & 31) == 0) red[t >> 5] = sq;
    __syncthreads();
    __shared__ float rn;
    if (t == 0) {
        double sum = 0.0;
        #pragma unroll
        for (int i = 0; i < 8; i++) sum += red[i];
        rn = (float)(1.0 / sqrt(sum));
    }
    __syncthreads();
    g_protn[r*256 + t] = v * rn;
}

// ---------------------------------------------------------------------------
// Kernel 2: instance-norm + cosine sim + argmax -> hard idx (one block per (p,n))
// ---------------------------------------------------------------------------
__global__ __launch_bounds__(256) void assign_kernel() {
    int p = blockIdx.x, n = blockIdx.y;
    extern __shared__ float sm[];
    float* Xs = sm;              // 16384
    float* P  = Xs + 16384;      // 1024
    float* MU = P + 1024;        // 256
    float* RS = MU + 256;        // 256
    int t = threadIdx.x;
    const float* src = g_xt + (size_t)(n*16 + p) * 16384;
    for (int i = t; i < 16384; i += 256) Xs[i] = src[i];
    const float* psrc = g_protn + p*1024;
    for (int i = t; i < 1024; i += 256) P[i] = psrc[i];
    __syncthreads();

    {
        double s1 = 0.0, s2 = 0.0;
        #pragma unroll 8
        for (int s = 0; s < 64; s++) {
            double v = (double)Xs[s*256 + t];
            s1 += v; s2 += v*v;
        }
        double mu = s1 / 64.0;
        double var = s2 / 64.0 - mu*mu;
        MU[t] = (float)mu;
        RS[t] = (float)(1.0 / sqrt(var + 1e-5));
    }
    __syncthreads();

    int w = t >> 5, lane = t & 31;
    for (int it = 0; it < 8; it++) {
        int s = w*8 + it;
        double nrm = 0.0, d0 = 0.0, d1 = 0.0, d2 = 0.0, d3 = 0.0;
        #pragma unroll
        for (int cc = 0; cc < 8; cc++) {
            int c = lane + 32*cc;
            float yf = (Xs[s*256 + c] - MU[c]) * RS[c];
            double y = (double)yf;
            nrm += y*y;
            d0 += y * (double)P[c];
            d1 += y * (double)P[256 + c];
            d2 += y * (double)P[512 + c];
            d3 += y * (double)P[768 + c];
        }
        #pragma unroll
        for (int off = 16; off > 0; off >>= 1) {
            nrm += __shfl_down_sync(0xffffffffu, nrm, off);
            d0  += __shfl_down_sync(0xffffffffu, d0, off);
            d1  += __shfl_down_sync(0xffffffffu, d1, off);
            d2  += __shfl_down_sync(0xffffffffu, d2, off);
            d3  += __shfl_down_sync(0xffffffffu, d3, off);
        }
        if (lane == 0) {
            double rn = 1.0 / sqrt(nrm);
            double sv0 = d0*rn, sv1 = d1*rn, sv2 = d2*rn, sv3 = d3*rn;
            int best = 0; double bv = sv0;
            if (sv1 > bv) { bv = sv1; best = 1; }
            if (sv2 > bv) { bv = sv2; best = 2; }
            if (sv3 > bv) { bv = sv3; best = 3; }
            g_idx[(p*64 + n)*64 + s] = (unsigned char)best;
        }
    }
}

// ---------------------------------------------------------------------------
// Kernel 3: mode over parts -> cluster_indices (as float)
// ---------------------------------------------------------------------------
__global__ void mode_kernel(float* __restrict__ outci) {
    int id = blockIdx.x*256 + threadIdx.x;
    if (id >= NN*SS) return;
    int n = id >> 6, s = id & 63;
    int c0 = 0, c1 = 0, c2 = 0, c3 = 0;
    #pragma unroll
    for (int p = 0; p < 16; p++) {
        int a = g_idx[(p*64 + n)*64 + s];
        c0 += (a == 0); c1 += (a == 1); c2 += (a == 2); c3 += (a == 3);
    }
    int best = 0, bc = c0;
    if (c1 > bc) { bc = c1; best = 1; }
    if (c2 > bc) { bc = c2; best = 2; }
    if (c3 > bc) { bc = c3; best = 3; }
    outci[id] = (float)best;
}

// ---------------------------------------------------------------------------
// Kernel 4: fused causal MHA + residual, one block per batch, 2 CTAs/SM
// smem: Xs[64][257] + B1/B2/S[64][65]  = 115712 B
// Persistent per-thread 8x8 accumulator carries the output projection
// across heads (no Os buffer, no second pass).
// ---------------------------------------------------------------------------
#define XST 257
#define BST 65
__global__ __launch_bounds__(256, 2) void attn_kernel(
    const float* __restrict__ Wq, const float* __restrict__ bq,
    const float* __restrict__ Wk, const float* __restrict__ bk,
    const float* __restrict__ Wv, const float* __restrict__ bv,
    const float* __restrict__ Wo, const float* __restrict__ bo) {
    extern __shared__ float sm[];
    float* Xs = sm;               // 64*257
    float* B1 = Xs + 64*XST;      // 64*65  (Q, then V)
    float* B2 = B1 + 64*BST;      // 64*65  (K, then head-out H)
    float* Ss = B2 + 64*BST;      // 64*65  (scores)
    int t = threadIdx.x;
    size_t b = blockIdx.x;
    const float* src = g_xt + b*16384;
    for (int i = t; i < 16384; i += 256)
        Xs[(i >> 8)*XST + (i & 255)] = src[i];
    __syncthreads();

    int j0 = t & 15, r0 = t >> 4;      // 16x16 thread grid: rows r0+16a, cols j0+16b
    int tc = t & 31, tr = t >> 5;      // outproj grid: rows tr+8a, cols tc*8..tc*8+7

    float acc[8][8];                   // persistent output-projection accumulator
    #pragma unroll
    for (int a = 0; a < 8; a++)
        #pragma unroll
        for (int c = 0; c < 8; c++) acc[a][c] = 0.f;

    for (int h = 0; h < 4; h++) {
        // ---- Q -> B1 ----
        {
            const float* W = Wq + h*64 + j0;
            float aq[4][4];
            #pragma unroll
            for (int a = 0; a < 4; a++)
                #pragma unroll
                for (int bb = 0; bb < 4; bb++) aq[a][bb] = 0.f;
            for (int i = 0; i < 256; i++) {
                float xv[4], wv[4];
                #pragma unroll
                for (int a = 0; a < 4; a++) xv[a] = Xs[(r0 + 16*a)*XST + i];
                #pragma unroll
                for (int bb = 0; bb < 4; bb++) wv[bb] = W[i*256 + 16*bb];
                #pragma unroll
                for (int a = 0; a < 4; a++)
                    #pragma unroll
                    for (int bb = 0; bb < 4; bb++)
                        aq[a][bb] = fmaf(xv[a], wv[bb], aq[a][bb]);
            }
            #pragma unroll
            for (int a = 0; a < 4; a++)
                #pragma unroll
                for (int bb = 0; bb < 4; bb++)
                    B1[(r0 + 16*a)*BST + j0 + 16*bb] = aq[a][bb] + bq[h*64 + j0 + 16*bb];
        }
        // ---- K -> B2 ----
        {
            const float* W = Wk + h*64 + j0;
            float ak[4][4];
            #pragma unroll
            for (int a = 0; a < 4; a++)
                #pragma unroll
                for (int bb = 0; bb < 4; bb++) ak[a][bb] = 0.f;
            for (int i = 0; i < 256; i++) {
                float xv[4], wv[4];
                #pragma unroll
                for (int a = 0; a < 4; a++) xv[a] = Xs[(r0 + 16*a)*XST + i];
                #pragma unroll
                for (int bb = 0; bb < 4; bb++) wv[bb] = W[i*256 + 16*bb];
                #pragma unroll
                for (int a = 0; a < 4; a++)
                    #pragma unroll
                    for (int bb = 0; bb < 4; bb++)
                        ak[a][bb] = fmaf(xv[a], wv[bb], ak[a][bb]);
            }
            #pragma unroll
            for (int a = 0; a < 4; a++)
                #pragma unroll
                for (int bb = 0; bb < 4; bb++)
                    B2[(r0 + 16*a)*BST + j0 + 16*bb] = ak[a][bb] + bk[h*64 + j0 + 16*bb];
        }
        __syncthreads();

        // ---- scores S = Q K^T * 0.125 ----
        {
            float as[4][4];
            #pragma unroll
            for (int a = 0; a < 4; a++)
                #pragma unroll
                for (int bb = 0; bb < 4; bb++) as[a][bb] = 0.f;
            for (int d = 0; d < 64; d++) {
                float qv[4], kv[4];
                #pragma unroll
                for (int a = 0; a < 4; a++) qv[a] = B1[(r0 + 16*a)*BST + d];
                #pragma unroll
                for (int bb = 0; bb < 4; bb++) kv[bb] = B2[(j0 + 16*bb)*BST + d];
                #pragma unroll
                for (int a = 0; a < 4; a++)
                    #pragma unroll
                    for (int bb = 0; bb < 4; bb++)
                        as[a][bb] = fmaf(qv[a], kv[bb], as[a][bb]);
            }
            #pragma unroll
            for (int a = 0; a < 4; a++)
                #pragma unroll
                for (int bb = 0; bb < 4; bb++)
                    Ss[(r0 + 16*a)*BST + j0 + 16*bb] = as[a][bb] * 0.125f;
        }
        __syncthreads();

        // ---- V -> B1 (Q dead) ----
        {
            const float* W = Wv + h*64 + j0;
            float av[4][4];
            #pragma unroll
            for (int a = 0; a < 4; a++)
                #pragma unroll
                for (int bb = 0; bb < 4; bb++) av[a][bb] = 0.f;
            for (int i = 0; i < 256; i++) {
                float xv[4], wv[4];
                #pragma unroll
                for (int a = 0; a < 4; a++) xv[a] = Xs[(r0 + 16*a)*XST + i];
                #pragma unroll
                for (int bb = 0; bb < 4; bb++) wv[bb] = W[i*256 + 16*bb];
                #pragma unroll
                for (int a = 0; a < 4; a++)
                    #pragma unroll
                    for (int bb = 0; bb < 4; bb++)
                        av[a][bb] = fmaf(xv[a], wv[bb], av[a][bb]);
            }
            #pragma unroll
            for (int a = 0; a < 4; a++)
                #pragma unroll
                for (int bb = 0; bb < 4; bb++)
                    B1[(r0 + 16*a)*BST + j0 + 16*bb] = av[a][bb] + bv[h*64 + j0 + 16*bb];
        }

        // ---- causal softmax, 4 threads per row ----
        {
            int row = t >> 2, sub = t & 3;
            float* Srow = Ss + row*BST;
            float m = -3.402823466e38f;
            for (int j = sub; j <= row; j += 4) m = fmaxf(m, Srow[j]);
            m = fmaxf(m, __shfl_xor_sync(0xffffffffu, m, 1));
            m = fmaxf(m, __shfl_xor_sync(0xffffffffu, m, 2));
            float ssum = 0.f;
            for (int j = sub; j < 64; j += 4) {
                if (j <= row) {
                    float e = __expf(Srow[j] - m);
                    Srow[j] = e; ssum += e;
                } else Srow[j] = 0.f;
            }
            ssum += __shfl_xor_sync(0xffffffffu, ssum, 1);
            ssum += __shfl_xor_sync(0xffffffffu, ssum, 2);
            float inv = 1.f / ssum;
            for (int j = sub; j <= row; j += 4) Srow[j] *= inv;
        }
        __syncthreads();

        // ---- head out H = S @ V -> B2 (K dead) ----
        {
            float ao[4][4];
            #pragma unroll
            for (int a = 0; a < 4; a++)
                #pragma unroll
                for (int bb = 0; bb < 4; bb++) ao[a][bb] = 0.f;
            for (int j = 0; j < 64; j++) {
                float sv[4], vv[4];
                #pragma unroll
                for (int a = 0; a < 4; a++) sv[a] = Ss[(r0 + 16*a)*BST + j];
                #pragma unroll
                for (int bb = 0; bb < 4; bb++) vv[bb] = B1[j*BST + j0 + 16*bb];
                #pragma unroll
                for (int a = 0; a < 4; a++)
                    #pragma unroll
                    for (int bb = 0; bb < 4; bb++)
                        ao[a][bb] = fmaf(sv[a], vv[bb], ao[a][bb]);
            }
            #pragma unroll
            for (int a = 0; a < 4; a++)
                #pragma unroll
                for (int bb = 0; bb < 4; bb++)
                    B2[(r0 + 16*a)*BST + j0 + 16*bb] = ao[a][bb];
        }
        __syncthreads();

        // ---- accumulate H @ Wo[h*64:(h+1)*64, :] into persistent acc ----
        {
            const float* Wob = Wo + (h*64)*256 + tc*8;
            for (int i = 0; i < 64; i++) {
                float ov[8];
                #pragma unroll
                for (int a = 0; a < 8; a++) ov[a] = B2[(tr + 8*a)*BST + i];
                float4 w0 = *(const float4*)(Wob + i*256);
                float4 w1 = *(const float4*)(Wob + i*256 + 4);
                #pragma unroll
                for (int a = 0; a < 8; a++) {
                    acc[a][0] = fmaf(ov[a], w0.x, acc[a][0]);
                    acc[a][1] = fmaf(ov[a], w0.y, acc[a][1]);
                    acc[a][2] = fmaf(ov[a], w0.z, acc[a][2]);
                    acc[a][3] = fmaf(ov[a], w0.w, acc[a][3]);
                    acc[a][4] = fmaf(ov[a], w1.x, acc[a][4]);
                    acc[a][5] = fmaf(ov[a], w1.y, acc[a][5]);
                    acc[a][6] = fmaf(ov[a], w1.z, acc[a][6]);
                    acc[a][7] = fmaf(ov[a], w1.w, acc[a][7]);
                }
            }
        }
        __syncthreads();
    }

    // ---- epilogue: + bo + X residual (from global), write g_xattn ----
    {
        float4 bo0 = *(const float4*)(bo + tc*8);
        float4 bo1 = *(const float4*)(bo + tc*8 + 4);
        const float* xg = g_xt + b*16384;
        float* dst = g_xattn + b*16384;
        #pragma unroll
        for (int a = 0; a < 8; a++) {
            int r = tr + 8*a;
            float4 x0 = *(const float4*)(xg + r*256 + tc*8);
            float4 x1 = *(const float4*)(xg + r*256 + tc*8 + 4);
            float4 o0, o1;
            o0.x = acc[a][0] + bo0.x + x0.x;
            o0.y = acc[a][1] + bo0.y + x0.y;
            o0.z = acc[a][2] + bo0.z + x0.z;
            o0.w = acc[a][3] + bo0.w + x0.w;
            o1.x = acc[a][4] + bo1.x + x1.x;
            o1.y = acc[a][5] + bo1.y + x1.y;
            o1.z = acc[a][6] + bo1.z + x1.z;
            o1.w = acc[a][7] + bo1.w + x1.w;
            *(float4*)(dst + r*256 + tc*8)     = o0;
            *(float4*)(dst + r*256 + tc*8 + 4) = o1;
        }
    }
}

// ---------------------------------------------------------------------------
// Kernel 5: scatter-max pooling
// ---------------------------------------------------------------------------
__global__ __launch_bounds__(256) void scatter_kernel() {
    int p = blockIdx.x, n = blockIdx.y, t = threadIdx.x;
    __shared__ unsigned char ids[64];
    if (t < 64) ids[t] = g_idx[(p*64 + n)*64 + t];
    __syncthreads();
    int c0 = 0, c1 = 0, c2 = 0, c3 = 0;
    #pragma unroll 8
    for (int s = 0; s < 64; s++) {
        int a = ids[s];
        c0 += (a == 0); c1 += (a == 1); c2 += (a == 2); c3 += (a == 3);
    }
    const float* src = g_xattn + (size_t)(n*16 + p)*16384 + t;
    float m0 = -3.402823466e38f, m1 = m0, m2 = m0, m3 = m0;
    #pragma unroll 8
    for (int s = 0; s < 64; s++) {
        float v = src[s*256];
        int a = ids[s];
        if (a == 0) m0 = fmaxf(m0, v);
        else if (a == 1) m1 = fmaxf(m1, v);
        else if (a == 2) m2 = fmaxf(m2, v);
        else m3 = fmaxf(m3, v);
    }
    if (c0 < 64) m0 = fmaxf(m0, 0.f);
    if (c1 < 64) m1 = fmaxf(m1, 0.f);
    if (c2 < 64) m2 = fmaxf(m2, 0.f);
    if (c3 < 64) m3 = fmaxf(m3, 0.f);
    float* dst = g_clustered + (size_t)(p*64 + n)*1024 + t;
    dst[0]   = m0;
    dst[256] = m1;
    dst[512] = m2;
    dst[768] = m3;
}

// ---------------------------------------------------------------------------
// Kernel 6: per-part FC
// ---------------------------------------------------------------------------
__global__ __launch_bounds__(256) void fc_kernel(const float* __restrict__ fcb,
                                                 float* __restrict__ out) {
    int p = blockIdx.x, n0 = blockIdx.y * 16, t = threadIdx.x;
    extern __shared__ float cl[];   // [16][1024]
    for (int nn = 0; nn < 16; nn++) {
        const float* src = g_clustered + (size_t)(p*64 + n0 + nn)*1024;
        for (int i = t; i < 1024; i += 256) cl[nn*1024 + i] = src[i];
    }
    __syncthreads();
    int o0 = t & 63, g = t >> 6;
    float acc[4][4];
    #pragma unroll
    for (int a = 0; a < 4; a++)
        #pragma unroll
        for (int bb = 0; bb < 4; bb++) acc[a][bb] = 0.f;
    const float* F = fcb + (size_t)p*1024*256 + o0;
    for (int kc = 0; kc < 1024; kc++) {
        float wv[4], cv[4];
        #pragma unroll
        for (int bb = 0; bb < 4; bb++) wv[bb] = F[(size_t)kc*256 + 64*bb];
        #pragma unroll
        for (int a = 0; a < 4; a++) cv[a] = cl[(g*4 + a)*1024 + kc];
        #pragma unroll
        for (int a = 0; a < 4; a++)
            #pragma unroll
            for (int bb = 0; bb < 4; bb++)
                acc[a][bb] = fmaf(cv[a], wv[bb], acc[a][bb]);
    }
    #pragma unroll
    for (int a = 0; a < 4; a++) {
        int n = n0 + g*4 + a;
        #pragma unroll
        for (int bb = 0; bb < 4; bb++) {
            int o = o0 + 64*bb;
            out[(size_t)n*4096 + o*16 + p] = acc[a][bb];
        }
    }
}

// ---------------------------------------------------------------------------
extern "C" void kernel_launch(void* const* d_in, const int* in_sizes, int n_in,
                              void* d_out, int out_size) {
    const float* x    = (const float*)d_in[0];
    const float* prot = (const float*)d_in[1];
    const float* Wq   = (const float*)d_in[2];
    const float* bq   = (const float*)d_in[3];
    const float* Wk   = (const float*)d_in[4];
    const float* bk   = (const float*)d_in[5];
    const float* Wv   = (const float*)d_in[6];
    const float* bv   = (const float*)d_in[7];
    const float* Wo   = (const float*)d_in[8];
    const float* bo   = (const float*)d_in[9];
    const float* fcb  = (const float*)d_in[10];
    float* out = (float*)d_out;

    const int ATTN_SMEM = (64*XST + 3*64*BST) * 4;   // 115712
    cudaFuncSetAttribute(attn_kernel, cudaFuncAttributeMaxDynamicSharedMemorySize, ATTN_SMEM);
    cudaFuncSetAttribute(assign_kernel, cudaFuncAttributeMaxDynamicSharedMemorySize, 71680);
    cudaFuncSetAttribute(fc_kernel, cudaFuncAttributeMaxDynamicSharedMemorySize, 65536);

    transpose_kernel<<<NN*SS, 256>>>(x);
    protonorm_kernel<<<PP*KK, 256>>>(prot);
    assign_kernel<<<dim3(PP, NN), 256, 71680>>>();
    if (out_size >= NN*CC*PP + NN*SS)
        mode_kernel<<<16, 256>>>(out + NN*CC*PP);
    attn_kernel<<<NB, 256, ATTN_SMEM>>>(Wq, bq, Wk, bk, Wv, bv, Wo, bo);
    scatter_kernel<<<dim3(PP, NN), 256>>>();
    fc_kernel<<<dim3(PP, 4), 256, 65536>>>(fcb, out);
}

// round 6
// speedup vs baseline: 1.8183x; 1.5360x over previous
#include <cuda_runtime.h>
#include <cuda_bf16.h>
#include <math.h>

// Problem constants
#define NN 64    // batch n
#define CC 256   // channels c
#define SS 64    // seq s
#define PP 16    // parts p
#define KK 4     // clusters k
#define NB (NN*PP)   // 1024 attention batches

// Scratch (no cudaMalloc allowed)
__device__ float g_xt[NB*SS*CC];        // (n,p,s,c) == (b,s,c)
__device__ float g_xattn[NB*SS*CC];     // attention out + residual
__device__ float g_protn[PP*KK*CC];
__device__ float g_clustered[PP*NN*KK*CC];
__device__ unsigned char g_idx[PP*NN*SS];
// packed bf16 hi/lo weights: [hi/lo][wsel(q,k,v,o)][128 kpair rows][256 cols]
__device__ unsigned g_pw[2*4*128*256];

// ---------------------------------------------------------------------------
// bf16 split helpers
// ---------------------------------------------------------------------------
__device__ __forceinline__ void split2(float v0, float v1, unsigned& hi, unsigned& lo) {
    __nv_bfloat16 h0 = __float2bfloat16(v0);
    __nv_bfloat16 h1 = __float2bfloat16(v1);
    float l0f = v0 - __bfloat162float(h0);
    float l1f = v1 - __bfloat162float(h1);
    __nv_bfloat16 l0 = __float2bfloat16(l0f);
    __nv_bfloat16 l1 = __float2bfloat16(l1f);
    hi = (unsigned)__bfloat16_as_ushort(h0) | ((unsigned)__bfloat16_as_ushort(h1) << 16);
    lo = (unsigned)__bfloat16_as_ushort(l0) | ((unsigned)__bfloat16_as_ushort(l1) << 16);
}

__device__ __forceinline__ void mma_bf16(float c[4], const unsigned a[4], unsigned b0, unsigned b1) {
    asm volatile(
        "mma.sync.aligned.m16n8k16.row.col.f32.bf16.bf16.f32 "
        "{%0,%1,%2,%3},{%4,%5,%6,%7},{%8,%9},{%0,%1,%2,%3};"
        : "+f"(c[0]), "+f"(c[1]), "+f"(c[2]), "+f"(c[3])
        : "r"(a[0]), "r"(a[1]), "r"(a[2]), "r"(a[3]), "r"(b0), "r"(b1));
}

// ---------------------------------------------------------------------------
// Kernel P: pack weights -> hi/lo bf16 pair arrays (pairs along k)
// ---------------------------------------------------------------------------
__global__ void packw_kernel(const float* __restrict__ Wq, const float* __restrict__ Wk,
                             const float* __restrict__ Wv, const float* __restrict__ Wo) {
    int n = threadIdx.x;           // 0..255
    int k2 = blockIdx.x;           // 0..127
    int ws = blockIdx.y;           // 0..3
    const float* W = (ws == 0) ? Wq : (ws == 1) ? Wk : (ws == 2) ? Wv : Wo;
    float v0 = W[(2*k2)*256 + n];
    float v1 = W[(2*k2 + 1)*256 + n];
    unsigned hi, lo;
    split2(v0, v1, hi, lo);
    g_pw[ws*32768 + k2*256 + n] = hi;
    g_pw[4*32768 + ws*32768 + k2*256 + n] = lo;
}

// ---------------------------------------------------------------------------
// Kernel 0: transpose x (n,c,s,p) -> g_xt (n,p,s,c)
// ---------------------------------------------------------------------------
__global__ void transpose_kernel(const float* __restrict__ x) {
    __shared__ float tile[256*17];
    int bx = blockIdx.x;
    int n = bx >> 6, s = bx & 63;
    int t = threadIdx.x;
    const float* src = x + (size_t)n*262144 + (size_t)s*16;
    #pragma unroll
    for (int w = 0; w < 16; w++) {
        int i = t + w*256;
        int c = i >> 4, pp = i & 15;
        tile[c*17 + pp] = src[(size_t)c*1024 + pp];
    }
    __syncthreads();
    float* dst = g_xt + (size_t)n*262144 + (size_t)s*256;
    #pragma unroll
    for (int w = 0; w < 16; w++) {
        dst[(size_t)w*16384 + t] = tile[t*17 + w];
    }
}

// ---------------------------------------------------------------------------
// Kernel 1: normalize prototypes
// ---------------------------------------------------------------------------
__global__ void protonorm_kernel(const float* __restrict__ prot) {
    int r = blockIdx.x;
    int t = threadIdx.x;
    float v = prot[r*256 + t];
    double sq = (double)v * (double)v;
    #pragma unroll
    for (int off = 16; off > 0; off >>= 1)
        sq += __shfl_down_sync(0xffffffffu, sq, off);
    __shared__ double red[8];
    if ((t & 31) == 0) red[t >> 5] = sq;
    __syncthreads();
    __shared__ float rn;
    if (t == 0) {
        double sum = 0.0;
        #pragma unroll
        for (int i = 0; i < 8; i++) sum += red[i];
        rn = (float)(1.0 / sqrt(sum));
    }
    __syncthreads();
    g_protn[r*256 + t] = v * rn;
}

// ---------------------------------------------------------------------------
// Kernel 2: instance-norm + cosine sim + argmax -> hard idx
// ---------------------------------------------------------------------------
__global__ __launch_bounds__(256) void assign_kernel() {
    int p = blockIdx.x, n = blockIdx.y;
    extern __shared__ float sm[];
    float* Xs = sm;
    float* P  = Xs + 16384;
    float* MU = P + 1024;
    float* RS = MU + 256;
    int t = threadIdx.x;
    const float* src = g_xt + (size_t)(n*16 + p) * 16384;
    for (int i = t; i < 16384; i += 256) Xs[i] = src[i];
    const float* psrc = g_protn + p*1024;
    for (int i = t; i < 1024; i += 256) P[i] = psrc[i];
    __syncthreads();

    {
        double s1 = 0.0, s2 = 0.0;
        #pragma unroll 8
        for (int s = 0; s < 64; s++) {
            double v = (double)Xs[s*256 + t];
            s1 += v; s2 += v*v;
        }
        double mu = s1 / 64.0;
        double var = s2 / 64.0 - mu*mu;
        MU[t] = (float)mu;
        RS[t] = (float)(1.0 / sqrt(var + 1e-5));
    }
    __syncthreads();

    int w = t >> 5, lane = t & 31;
    for (int it = 0; it < 8; it++) {
        int s = w*8 + it;
        double nrm = 0.0, d0 = 0.0, d1 = 0.0, d2 = 0.0, d3 = 0.0;
        #pragma unroll
        for (int cc = 0; cc < 8; cc++) {
            int c = lane + 32*cc;
            float yf = (Xs[s*256 + c] - MU[c]) * RS[c];
            double y = (double)yf;
            nrm += y*y;
            d0 += y * (double)P[c];
            d1 += y * (double)P[256 + c];
            d2 += y * (double)P[512 + c];
            d3 += y * (double)P[768 + c];
        }
        #pragma unroll
        for (int off = 16; off > 0; off >>= 1) {
            nrm += __shfl_down_sync(0xffffffffu, nrm, off);
            d0  += __shfl_down_sync(0xffffffffu, d0, off);
            d1  += __shfl_down_sync(0xffffffffu, d1, off);
            d2  += __shfl_down_sync(0xffffffffu, d2, off);
            d3  += __shfl_down_sync(0xffffffffu, d3, off);
        }
        if (lane == 0) {
            double rn = 1.0 / sqrt(nrm);
            double sv0 = d0*rn, sv1 = d1*rn, sv2 = d2*rn, sv3 = d3*rn;
            int best = 0; double bv = sv0;
            if (sv1 > bv) { bv = sv1; best = 1; }
            if (sv2 > bv) { bv = sv2; best = 2; }
            if (sv3 > bv) { bv = sv3; best = 3; }
            g_idx[(p*64 + n)*64 + s] = (unsigned char)best;
        }
    }
}

// ---------------------------------------------------------------------------
// Kernel 3: mode over parts -> cluster_indices (as float)
// ---------------------------------------------------------------------------
__global__ void mode_kernel(float* __restrict__ outci) {
    int id = blockIdx.x*256 + threadIdx.x;
    if (id >= NN*SS) return;
    int n = id >> 6, s = id & 63;
    int c0 = 0, c1 = 0, c2 = 0, c3 = 0;
    #pragma unroll
    for (int p = 0; p < 16; p++) {
        int a = g_idx[(p*64 + n)*64 + s];
        c0 += (a == 0); c1 += (a == 1); c2 += (a == 2); c3 += (a == 3);
    }
    int best = 0, bc = c0;
    if (c1 > bc) { bc = c1; best = 1; }
    if (c2 > bc) { bc = c2; best = 2; }
    if (c3 > bc) { bc = c3; best = 3; }
    outci[id] = (float)best;
}

// ---------------------------------------------------------------------------
// Kernel 4: fused causal MHA + residual, tensor cores (bf16x3 split emulation)
// One 512-thread CTA per batch. smem u32 layout offsets:
// ---------------------------------------------------------------------------
#define XHI 0           // X hi plane: 64 rows x 132 u32 (pairs along c)
#define XLO 8448
#define QHI 16896       // Q planes (later S probs): 64 x 36 u32
#define QLO 19200
#define KHI 21504       // K planes (later H): 64 x 36 u32
#define KLO 23808
#define VHI 26112       // V transposed planes: [dim][s-pair] 64 x 36 u32
#define VLO 28416
#define VFO 30720       // V fp32 staging: 64 x 66 floats
#define SSO 34944       // scores fp32: 64 x 66 floats
#define SMEM_U32 39168  // 156672 bytes

__global__ __launch_bounds__(512, 1) void attn_kernel(
    const float* __restrict__ bq, const float* __restrict__ bk,
    const float* __restrict__ bv, const float* __restrict__ bo) {
    extern __shared__ unsigned smu[];
    float* VFf = (float*)(smu + VFO);
    float* SSf = (float*)(smu + SSO);
    int t = threadIdx.x;
    int w = t >> 5, lane = t & 31;
    int g = lane >> 2, tg = lane & 3;       // groupID, thread-in-group
    size_t b = blockIdx.x;

    // ---- load X, split into bf16 hi/lo pair planes ----
    {
        const float2* src = (const float2*)(g_xt + b*16384);
        for (int idx = t; idx < 8192; idx += 512) {
            int r = idx >> 7, c2 = idx & 127;
            float2 v = src[idx];
            unsigned hi, lo;
            split2(v.x, v.y, hi, lo);
            smu[XHI + r*132 + c2] = hi;
            smu[XLO + r*132 + c2] = lo;
        }
    }
    __syncthreads();

    int mt = w >> 2;                 // m-tile for this warp
    int rowA = mt*16 + g;            // fragment row (and +8)
    int wq4 = w & 3;

    float oacc[8][4];                // persistent output-projection accum
    #pragma unroll
    for (int i = 0; i < 8; i++)
        #pragma unroll
        for (int j = 0; j < 4; j++) oacc[i][j] = 0.f;

    const unsigned* pwo_hi = g_pw + 3*32768;
    const unsigned* pwo_lo = g_pw + 7*32768;

    for (int h = 0; h < 4; h++) {
        // ================= merged QKV projection: 64 x 192 x 256 =========
        {
            float acc[6][4];
            #pragma unroll
            for (int i = 0; i < 6; i++)
                #pragma unroll
                for (int j = 0; j < 4; j++) acc[i][j] = 0.f;

            const unsigned* bh[6];
            #pragma unroll
            for (int i = 0; i < 6; i++) {
                int nt = 6*wq4 + i;
                int sel = nt >> 3;                       // 0=Q 1=K 2=V
                int gcol = h*64 + (nt & 7)*8 + g;
                bh[i] = g_pw + sel*32768 + gcol;         // lo = +4*32768
            }

            for (int kt = 0; kt < 16; kt++) {
                unsigned ah[4], al[4];
                int base = rowA*132 + 8*kt + tg;
                ah[0] = smu[XHI + base];
                ah[1] = smu[XHI + base + 8*132];
                ah[2] = smu[XHI + base + 4];
                ah[3] = smu[XHI + base + 8*132 + 4];
                al[0] = smu[XLO + base];
                al[1] = smu[XLO + base + 8*132];
                al[2] = smu[XLO + base + 4];
                al[3] = smu[XLO + base + 8*132 + 4];
                int r0 = (8*kt + tg)*256;
                int r1 = (8*kt + 4 + tg)*256;
                #pragma unroll
                for (int i = 0; i < 6; i++) {
                    unsigned bh0 = bh[i][r0], bh1 = bh[i][r1];
                    unsigned bl0 = bh[i][4*32768 + r0], bl1 = bh[i][4*32768 + r1];
                    mma_bf16(acc[i], ah, bh0, bh1);
                    mma_bf16(acc[i], ah, bl0, bl1);
                    mma_bf16(acc[i], al, bh0, bh1);
                }
            }

            // store: Q,K -> split planes; V -> fp32 staging
            #pragma unroll
            for (int i = 0; i < 6; i++) {
                int nt = 6*wq4 + i;
                int sel = nt >> 3;
                int lcol = (nt & 7)*8 + 2*tg;            // local col in 0..63
                const float* bias = (sel == 0) ? bq : (sel == 1) ? bk : bv;
                float bz0 = bias[h*64 + lcol], bz1 = bias[h*64 + lcol + 1];
                float c0 = acc[i][0] + bz0, c1 = acc[i][1] + bz1;
                float c2 = acc[i][2] + bz0, c3 = acc[i][3] + bz1;
                if (sel < 2) {
                    int plane = (sel == 0) ? QHI : KHI;
                    int uidx = lcol >> 1;
                    unsigned hi, lo;
                    split2(c0, c1, hi, lo);
                    smu[plane + rowA*36 + uidx] = hi;
                    smu[plane + 2304 + rowA*36 + uidx] = lo;
                    split2(c2, c3, hi, lo);
                    smu[plane + (rowA + 8)*36 + uidx] = hi;
                    smu[plane + 2304 + (rowA + 8)*36 + uidx] = lo;
                } else {
                    *(float2*)(VFf + rowA*66 + lcol) = make_float2(c0, c1);
                    *(float2*)(VFf + (rowA + 8)*66 + lcol) = make_float2(c2, c3);
                }
            }
        }
        __syncthreads();

        // ====== repack V (transpose: pairs along s) + scores concurrently ===
        for (int idx = t; idx < 2048; idx += 512) {
            int dim = idx >> 5, sh = idx & 31;
            float v0 = VFf[(2*sh)*66 + dim];
            float v1 = VFf[(2*sh + 1)*66 + dim];
            unsigned hi, lo;
            split2(v0, v1, hi, lo);
            smu[VHI + dim*36 + sh] = hi;
            smu[VLO + dim*36 + sh] = lo;
        }
        // scores S = Q K^T * 0.125 : 64x64x64, 2 tiles per warp
        {
            float sacc[2][4];
            #pragma unroll
            for (int i = 0; i < 2; i++)
                #pragma unroll
                for (int j = 0; j < 4; j++) sacc[i][j] = 0.f;
            for (int kt = 0; kt < 4; kt++) {
                unsigned ah[4], al[4];
                int base = rowA*36 + 8*kt + tg;
                ah[0] = smu[QHI + base];       ah[1] = smu[QHI + base + 8*36];
                ah[2] = smu[QHI + base + 4];   ah[3] = smu[QHI + base + 8*36 + 4];
                al[0] = smu[QLO + base];       al[1] = smu[QLO + base + 8*36];
                al[2] = smu[QLO + base + 4];   al[3] = smu[QLO + base + 8*36 + 4];
                #pragma unroll
                for (int i = 0; i < 2; i++) {
                    int key = (2*wq4 + i)*8 + g;
                    int bb = key*36 + 8*kt + tg;
                    unsigned bh0 = smu[KHI + bb], bh1 = smu[KHI + bb + 4];
                    unsigned bl0 = smu[KLO + bb], bl1 = smu[KLO + bb + 4];
                    mma_bf16(sacc[i], ah, bh0, bh1);
                    mma_bf16(sacc[i], ah, bl0, bl1);
                    mma_bf16(sacc[i], al, bh0, bh1);
                }
            }
            #pragma unroll
            for (int i = 0; i < 2; i++) {
                int col = (2*wq4 + i)*8 + 2*tg;
                *(float2*)(SSf + rowA*66 + col) =
                    make_float2(sacc[i][0]*0.125f, sacc[i][1]*0.125f);
                *(float2*)(SSf + (rowA + 8)*66 + col) =
                    make_float2(sacc[i][2]*0.125f, sacc[i][3]*0.125f);
            }
        }
        __syncthreads();

        // ====== causal softmax, 8 threads per row ======
        {
            int row = t >> 3, sub = t & 7;
            float* Srow = SSf + row*66;
            float m = -3.402823466e38f;
            for (int j = sub; j <= row; j += 8) m = fmaxf(m, Srow[j]);
            m = fmaxf(m, __shfl_xor_sync(0xffffffffu, m, 1));
            m = fmaxf(m, __shfl_xor_sync(0xffffffffu, m, 2));
            m = fmaxf(m, __shfl_xor_sync(0xffffffffu, m, 4));
            float ssum = 0.f;
            for (int j = sub; j < 64; j += 8) {
                if (j <= row) {
                    float e = __expf(Srow[j] - m);
                    Srow[j] = e; ssum += e;
                } else Srow[j] = 0.f;
            }
            ssum += __shfl_xor_sync(0xffffffffu, ssum, 1);
            ssum += __shfl_xor_sync(0xffffffffu, ssum, 2);
            ssum += __shfl_xor_sync(0xffffffffu, ssum, 4);
            float inv = 1.f / ssum;
            for (int j = sub; j <= row; j += 8) Srow[j] *= inv;
        }
        __syncthreads();

        // ====== pack probs into S planes (alias Q planes) ======
        for (int idx = t; idx < 2048; idx += 512) {
            int r = idx >> 5, jh = idx & 31;
            float v0 = SSf[r*66 + 2*jh];
            float v1 = SSf[r*66 + 2*jh + 1];
            unsigned hi, lo;
            split2(v0, v1, hi, lo);
            smu[QHI + r*36 + jh] = hi;
            smu[QLO + r*36 + jh] = lo;
        }
        __syncthreads();

        // ====== H = S @ V -> H planes (alias K planes) ======
        {
            float hacc[2][4];
            #pragma unroll
            for (int i = 0; i < 2; i++)
                #pragma unroll
                for (int j = 0; j < 4; j++) hacc[i][j] = 0.f;
            for (int kt = 0; kt < 4; kt++) {
                unsigned ah[4], al[4];
                int base = rowA*36 + 8*kt + tg;
                ah[0] = smu[QHI + base];       ah[1] = smu[QHI + base + 8*36];
                ah[2] = smu[QHI + base + 4];   ah[3] = smu[QHI + base + 8*36 + 4];
                al[0] = smu[QLO + base];       al[1] = smu[QLO + base + 8*36];
                al[2] = smu[QLO + base + 4];   al[3] = smu[QLO + base + 8*36 + 4];
                #pragma unroll
                for (int i = 0; i < 2; i++) {
                    int dim = (2*wq4 + i)*8 + g;
                    int bb = dim*36 + 8*kt + tg;
                    unsigned bh0 = smu[VHI + bb], bh1 = smu[VHI + bb + 4];
                    unsigned bl0 = smu[VLO + bb], bl1 = smu[VLO + bb + 4];
                    mma_bf16(hacc[i], ah, bh0, bh1);
                    mma_bf16(hacc[i], ah, bl0, bl1);
                    mma_bf16(hacc[i], al, bh0, bh1);
                }
            }
            __syncthreads();   // K planes dead, safe to overwrite as H
            #pragma unroll
            for (int i = 0; i < 2; i++) {
                int lcol = (2*wq4 + i)*8 + 2*tg;
                int uidx = lcol >> 1;
                unsigned hi, lo;
                split2(hacc[i][0], hacc[i][1], hi, lo);
                smu[KHI + rowA*36 + uidx] = hi;
                smu[KLO + rowA*36 + uidx] = lo;
                split2(hacc[i][2], hacc[i][3], hi, lo);
                smu[KHI + (rowA + 8)*36 + uidx] = hi;
                smu[KLO + (rowA + 8)*36 + uidx] = lo;
            }
        }
        __syncthreads();

        // ====== accumulate H @ Wo[h*64:(h+1)*64, :] into oacc ======
        {
            for (int kt = 0; kt < 4; kt++) {
                unsigned ah[4], al[4];
                int base = rowA*36 + 8*kt + tg;
                ah[0] = smu[KHI + base];       ah[1] = smu[KHI + base + 8*36];
                ah[2] = smu[KHI + base + 4];   ah[3] = smu[KHI + base + 8*36 + 4];
                al[0] = smu[KLO + base];       al[1] = smu[KLO + base + 8*36];
                al[2] = smu[KLO + base + 4];   al[3] = smu[KLO + base + 8*36 + 4];
                int r0 = (h*32 + 8*kt + tg)*256;
                int r1 = (h*32 + 8*kt + 4 + tg)*256;
                #pragma unroll
                for (int i = 0; i < 8; i++) {
                    int ncol = wq4*64 + 8*i + g;
                    unsigned bh0 = pwo_hi[r0 + ncol], bh1 = pwo_hi[r1 + ncol];
                    unsigned bl0 = pwo_lo[r0 + ncol], bl1 = pwo_lo[r1 + ncol];
                    mma_bf16(oacc[i], ah, bh0, bh1);
                    mma_bf16(oacc[i], ah, bl0, bl1);
                    mma_bf16(oacc[i], al, bh0, bh1);
                }
            }
        }
        __syncthreads();   // before next head overwrites planes
    }

    // ---- epilogue: + bo + residual (global fp32), write g_xattn ----
    {
        const float* xg = g_xt + b*16384;
        float* dst = g_xattn + b*16384;
        #pragma unroll
        for (int i = 0; i < 8; i++) {
            int col = wq4*64 + 8*i + 2*tg;
            float b0 = bo[col], b1 = bo[col + 1];
            float2 rA = *(const float2*)(xg + rowA*256 + col);
            float2 rB = *(const float2*)(xg + (rowA + 8)*256 + col);
            *(float2*)(dst + rowA*256 + col) =
                make_float2(oacc[i][0] + b0 + rA.x, oacc[i][1] + b1 + rA.y);
            *(float2*)(dst + (rowA + 8)*256 + col) =
                make_float2(oacc[i][2] + b0 + rB.x, oacc[i][3] + b1 + rB.y);
        }
    }
}

// ---------------------------------------------------------------------------
// Kernel 5: scatter-max pooling
// ---------------------------------------------------------------------------
__global__ __launch_bounds__(256) void scatter_kernel() {
    int p = blockIdx.x, n = blockIdx.y, t = threadIdx.x;
    __shared__ unsigned char ids[64];
    if (t < 64) ids[t] = g_idx[(p*64 + n)*64 + t];
    __syncthreads();
    int c0 = 0, c1 = 0, c2 = 0, c3 = 0;
    #pragma unroll 8
    for (int s = 0; s < 64; s++) {
        int a = ids[s];
        c0 += (a == 0); c1 += (a == 1); c2 += (a == 2); c3 += (a == 3);
    }
    const float* src = g_xattn + (size_t)(n*16 + p)*16384 + t;
    float m0 = -3.402823466e38f, m1 = m0, m2 = m0, m3 = m0;
    #pragma unroll 8
    for (int s = 0; s < 64; s++) {
        float v = src[s*256];
        int a = ids[s];
        if (a == 0) m0 = fmaxf(m0, v);
        else if (a == 1) m1 = fmaxf(m1, v);
        else if (a == 2) m2 = fmaxf(m2, v);
        else m3 = fmaxf(m3, v);
    }
    if (c0 < 64) m0 = fmaxf(m0, 0.f);
    if (c1 < 64) m1 = fmaxf(m1, 0.f);
    if (c2 < 64) m2 = fmaxf(m2, 0.f);
    if (c3 < 64) m3 = fmaxf(m3, 0.f);
    float* dst = g_clustered + (size_t)(p*64 + n)*1024 + t;
    dst[0]   = m0;
    dst[256] = m1;
    dst[512] = m2;
    dst[768] = m3;
}

// ---------------------------------------------------------------------------
// Kernel 6: per-part FC
// ---------------------------------------------------------------------------
__global__ __launch_bounds__(256) void fc_kernel(const float* __restrict__ fcb,
                                                 float* __restrict__ out) {
    int p = blockIdx.x, n0 = blockIdx.y * 16, t = threadIdx.x;
    extern __shared__ float cl[];
    for (int nn = 0; nn < 16; nn++) {
        const float* src = g_clustered + (size_t)(p*64 + n0 + nn)*1024;
        for (int i = t; i < 1024; i += 256) cl[nn*1024 + i] = src[i];
    }
    __syncthreads();
    int o0 = t & 63, g = t >> 6;
    float acc[4][4];
    #pragma unroll
    for (int a = 0; a < 4; a++)
        #pragma unroll
        for (int bb = 0; bb < 4; bb++) acc[a][bb] = 0.f;
    const float* F = fcb + (size_t)p*1024*256 + o0;
    for (int kc = 0; kc < 1024; kc++) {
        float wv[4], cv[4];
        #pragma unroll
        for (int bb = 0; bb < 4; bb++) wv[bb] = F[(size_t)kc*256 + 64*bb];
        #pragma unroll
        for (int a = 0; a < 4; a++) cv[a] = cl[(g*4 + a)*1024 + kc];
        #pragma unroll
        for (int a = 0; a < 4; a++)
            #pragma unroll
            for (int bb = 0; bb < 4; bb++)
                acc[a][bb] = fmaf(cv[a], wv[bb], acc[a][bb]);
    }
    #pragma unroll
    for (int a = 0; a < 4; a++) {
        int n = n0 + g*4 + a;
        #pragma unroll
        for (int bb = 0; bb < 4; bb++) {
            int o = o0 + 64*bb;
            out[(size_t)n*4096 + o*16 + p] = acc[a][bb];
        }
    }
}

// ---------------------------------------------------------------------------
extern "C" void kernel_launch(void* const* d_in, const int* in_sizes, int n_in,
                              void* d_out, int out_size) {
    const float* x    = (const float*)d_in[0];
    const float* prot = (const float*)d_in[1];
    const float* Wq   = (const float*)d_in[2];
    const float* bq   = (const float*)d_in[3];
    const float* Wk   = (const float*)d_in[4];
    const float* bk   = (const float*)d_in[5];
    const float* Wv   = (const float*)d_in[6];
    const float* bv   = (const float*)d_in[7];
    const float* Wo   = (const float*)d_in[8];
    const float* bo   = (const float*)d_in[9];
    const float* fcb  = (const float*)d_in[10];
    float* out = (float*)d_out;

    cudaFuncSetAttribute(attn_kernel, cudaFuncAttributeMaxDynamicSharedMemorySize, SMEM_U32*4);
    cudaFuncSetAttribute(assign_kernel, cudaFuncAttributeMaxDynamicSharedMemorySize, 71680);
    cudaFuncSetAttribute(fc_kernel, cudaFuncAttributeMaxDynamicSharedMemorySize, 65536);

    packw_kernel<<<dim3(128, 4), 256>>>(Wq, Wk, Wv, Wo);
    transpose_kernel<<<NN*SS, 256>>>(x);
    protonorm_kernel<<<PP*KK, 256>>>(prot);
    assign_kernel<<<dim3(PP, NN), 256, 71680>>>();
    if (out_size >= NN*CC*PP + NN*SS)
        mode_kernel<<<16, 256>>>(out + NN*CC*PP);
    attn_kernel<<<NB, 512, SMEM_U32*4>>>(bq, bk, bv, bo);
    scatter_kernel<<<dim3(PP, NN), 256>>>();
    fc_kernel<<<dim3(PP, 4), 256, 65536>>>(fcb, out);
}

// round 8
// speedup vs baseline: 2.7793x; 1.5285x over previous
#include <cuda_runtime.h>
#include <cuda_bf16.h>
#include <math.h>

// Problem constants
#define NN 64    // batch n
#define CC 256   // channels c
#define SS 64    // seq s
#define PP 16    // parts p
#define KK 4     // clusters k
#define NB (NN*PP)   // 1024 attention batches

// Scratch (no cudaMalloc allowed)
__device__ float g_xt[NB*SS*CC];        // (n,p,s,c) == (b,s,c)
__device__ float g_xattn[NB*SS*CC];     // attention out + residual
__device__ float g_protn[PP*KK*CC];
__device__ float g_clustered[PP*NN*KK*CC];
__device__ unsigned char g_idx[PP*NN*SS];
// packed bf16 hi/lo weights: [hi/lo][wsel(q,k,v,o)][128 kpair rows][256 cols]
__device__ unsigned g_pw[2*4*128*256];

// ---------------------------------------------------------------------------
// bf16 split helpers
// ---------------------------------------------------------------------------
__device__ __forceinline__ void split2(float v0, float v1, unsigned& hi, unsigned& lo) {
    __nv_bfloat16 h0 = __float2bfloat16(v0);
    __nv_bfloat16 h1 = __float2bfloat16(v1);
    float l0f = v0 - __bfloat162float(h0);
    float l1f = v1 - __bfloat162float(h1);
    __nv_bfloat16 l0 = __float2bfloat16(l0f);
    __nv_bfloat16 l1 = __float2bfloat16(l1f);
    hi = (unsigned)__bfloat16_as_ushort(h0) | ((unsigned)__bfloat16_as_ushort(h1) << 16);
    lo = (unsigned)__bfloat16_as_ushort(l0) | ((unsigned)__bfloat16_as_ushort(l1) << 16);
}

__device__ __forceinline__ void mma_bf16(float c[4], const unsigned a[4], unsigned b0, unsigned b1) {
    asm volatile(
        "mma.sync.aligned.m16n8k16.row.col.f32.bf16.bf16.f32 "
        "{%0,%1,%2,%3},{%4,%5,%6,%7},{%8,%9},{%0,%1,%2,%3};"
        : "+f"(c[0]), "+f"(c[1]), "+f"(c[2]), "+f"(c[3])
        : "r"(a[0]), "r"(a[1]), "r"(a[2]), "r"(a[3]), "r"(b0), "r"(b1));
}

// ---------------------------------------------------------------------------
// Kernel P: pack weights -> hi/lo bf16 pair arrays (pairs along k)
// ---------------------------------------------------------------------------
__global__ void packw_kernel(const float* __restrict__ Wq, const float* __restrict__ Wk,
                             const float* __restrict__ Wv, const float* __restrict__ Wo) {
    int n = threadIdx.x;
    int k2 = blockIdx.x;
    int ws = blockIdx.y;
    const float* W = (ws == 0) ? Wq : (ws == 1) ? Wk : (ws == 2) ? Wv : Wo;
    float v0 = W[(2*k2)*256 + n];
    float v1 = W[(2*k2 + 1)*256 + n];
    unsigned hi, lo;
    split2(v0, v1, hi, lo);
    g_pw[ws*32768 + k2*256 + n] = hi;
    g_pw[4*32768 + ws*32768 + k2*256 + n] = lo;
}

// ---------------------------------------------------------------------------
// Kernel 0: transpose x (n,c,s,p) -> g_xt (n,p,s,c)
// ---------------------------------------------------------------------------
__global__ void transpose_kernel(const float* __restrict__ x) {
    __shared__ float tile[256*17];
    int bx = blockIdx.x;
    int n = bx >> 6, s = bx & 63;
    int t = threadIdx.x;
    const float* src = x + (size_t)n*262144 + (size_t)s*16;
    #pragma unroll
    for (int w = 0; w < 16; w++) {
        int i = t + w*256;
        int c = i >> 4, pp = i & 15;
        tile[c*17 + pp] = src[(size_t)c*1024 + pp];
    }
    __syncthreads();
    float* dst = g_xt + (size_t)n*262144 + (size_t)s*256;
    #pragma unroll
    for (int w = 0; w < 16; w++) {
        dst[(size_t)w*16384 + t] = tile[t*17 + w];
    }
}

// ---------------------------------------------------------------------------
// Kernel 1: normalize prototypes
// ---------------------------------------------------------------------------
__global__ void protonorm_kernel(const float* __restrict__ prot) {
    int r = blockIdx.x;
    int t = threadIdx.x;
    float v = prot[r*256 + t];
    float sq = v * v;
    #pragma unroll
    for (int off = 16; off > 0; off >>= 1)
        sq += __shfl_down_sync(0xffffffffu, sq, off);
    __shared__ float red[8];
    if ((t & 31) == 0) red[t >> 5] = sq;
    __syncthreads();
    __shared__ float rn;
    if (t == 0) {
        float sum = 0.f;
        #pragma unroll
        for (int i = 0; i < 8; i++) sum += red[i];
        rn = rsqrtf(sum);
    }
    __syncthreads();
    g_protn[r*256 + t] = v * rn;
}

// ---------------------------------------------------------------------------
// Kernel 2: instance-norm + dot + argmax -> hard idx (one block per (p,n))
// All fp32; skips the y-norm (argmax-invariant) and the rsqrt.
// ---------------------------------------------------------------------------
__global__ __launch_bounds__(256) void assign_kernel() {
    int p = blockIdx.x, n = blockIdx.y;
    extern __shared__ float sm[];
    float* Xs = sm;              // 16384 floats
    float* P  = Xs + 16384;      // 1024
    float* MU = P + 1024;        // 256
    float* RS = MU + 256;        // 256
    int t = threadIdx.x;
    const float* src = g_xt + (size_t)(n*16 + p) * 16384;
    for (int i = t; i < 16384; i += 256) Xs[i] = src[i];
    const float* psrc = g_protn + p*1024;
    for (int i = t; i < 1024; i += 256) P[i] = psrc[i];
    __syncthreads();

    // per-channel mean/var over s (thread t = channel), fp32
    {
        float s1 = 0.f, s2 = 0.f;
        #pragma unroll
        for (int s = 0; s < 64; s++) {
            float v = Xs[s*256 + t];
            s1 += v; s2 += v*v;
        }
        float mu = s1 * 0.015625f;
        float var = s2 * 0.015625f - mu*mu;
        MU[t] = mu;
        RS[t] = rsqrtf(var + 1e-5f);
    }
    __syncthreads();

    int w = t >> 5, lane = t & 31;
    #pragma unroll
    for (int it = 0; it < 8; it++) {
        int s = w*8 + it;
        float d0 = 0.f, d1 = 0.f, d2 = 0.f, d3 = 0.f;
        #pragma unroll
        for (int cc = 0; cc < 8; cc++) {
            int c = lane + 32*cc;
            float y = (Xs[s*256 + c] - MU[c]) * RS[c];
            d0 = fmaf(y, P[c],       d0);
            d1 = fmaf(y, P[256 + c], d1);
            d2 = fmaf(y, P[512 + c], d2);
            d3 = fmaf(y, P[768 + c], d3);
        }
        #pragma unroll
        for (int off = 16; off > 0; off >>= 1) {
            d0 += __shfl_down_sync(0xffffffffu, d0, off);
            d1 += __shfl_down_sync(0xffffffffu, d1, off);
            d2 += __shfl_down_sync(0xffffffffu, d2, off);
            d3 += __shfl_down_sync(0xffffffffu, d3, off);
        }
        if (lane == 0) {
            int best = 0; float bv = d0;
            if (d1 > bv) { bv = d1; best = 1; }
            if (d2 > bv) { bv = d2; best = 2; }
            if (d3 > bv) { bv = d3; best = 3; }
            g_idx[(p*64 + n)*64 + s] = (unsigned char)best;
        }
    }
}

// ---------------------------------------------------------------------------
// Kernel 3: mode over parts -> cluster_indices (as float)
// ---------------------------------------------------------------------------
__global__ void mode_kernel(float* __restrict__ outci) {
    int id = blockIdx.x*256 + threadIdx.x;
    if (id >= NN*SS) return;
    int n = id >> 6, s = id & 63;
    int c0 = 0, c1 = 0, c2 = 0, c3 = 0;
    #pragma unroll
    for (int p = 0; p < 16; p++) {
        int a = g_idx[(p*64 + n)*64 + s];
        c0 += (a == 0); c1 += (a == 1); c2 += (a == 2); c3 += (a == 3);
    }
    int best = 0, bc = c0;
    if (c1 > bc) { bc = c1; best = 1; }
    if (c2 > bc) { bc = c2; best = 2; }
    if (c3 > bc) { bc = c3; best = 3; }
    outci[id] = (float)best;
}

// ---------------------------------------------------------------------------
// Kernel 4: fused causal MHA + residual, tensor cores (bf16x3 split emulation)
// ---------------------------------------------------------------------------
#define XHI 0
#define XLO 8448
#define QHI 16896
#define QLO 19200
#define KHI 21504
#define KLO 23808
#define VHI 26112
#define VLO 28416
#define VFO 30720
#define SSO 34944
#define SMEM_U32 39168

__global__ __launch_bounds__(512, 1) void attn_kernel(
    const float* __restrict__ bq, const float* __restrict__ bk,
    const float* __restrict__ bv, const float* __restrict__ bo) {
    extern __shared__ unsigned smu[];
    float* VFf = (float*)(smu + VFO);
    float* SSf = (float*)(smu + SSO);
    int t = threadIdx.x;
    int w = t >> 5, lane = t & 31;
    int g = lane >> 2, tg = lane & 3;
    size_t b = blockIdx.x;

    {
        const float2* src = (const float2*)(g_xt + b*16384);
        for (int idx = t; idx < 8192; idx += 512) {
            int r = idx >> 7, c2 = idx & 127;
            float2 v = src[idx];
            unsigned hi, lo;
            split2(v.x, v.y, hi, lo);
            smu[XHI + r*132 + c2] = hi;
            smu[XLO + r*132 + c2] = lo;
        }
    }
    __syncthreads();

    int mt = w >> 2;
    int rowA = mt*16 + g;
    int wq4 = w & 3;

    float oacc[8][4];
    #pragma unroll
    for (int i = 0; i < 8; i++)
        #pragma unroll
        for (int j = 0; j < 4; j++) oacc[i][j] = 0.f;

    const unsigned* pwo_hi = g_pw + 3*32768;
    const unsigned* pwo_lo = g_pw + 7*32768;

    for (int h = 0; h < 4; h++) {
        // ================= merged QKV projection =========
        {
            float acc[6][4];
            #pragma unroll
            for (int i = 0; i < 6; i++)
                #pragma unroll
                for (int j = 0; j < 4; j++) acc[i][j] = 0.f;

            const unsigned* bh[6];
            #pragma unroll
            for (int i = 0; i < 6; i++) {
                int nt = 6*wq4 + i;
                int sel = nt >> 3;
                int gcol = h*64 + (nt & 7)*8 + g;
                bh[i] = g_pw + sel*32768 + gcol;
            }

            for (int kt = 0; kt < 16; kt++) {
                unsigned ah[4], al[4];
                int base = rowA*132 + 8*kt + tg;
                ah[0] = smu[XHI + base];
                ah[1] = smu[XHI + base + 8*132];
                ah[2] = smu[XHI + base + 4];
                ah[3] = smu[XHI + base + 8*132 + 4];
                al[0] = smu[XLO + base];
                al[1] = smu[XLO + base + 8*132];
                al[2] = smu[XLO + base + 4];
                al[3] = smu[XLO + base + 8*132 + 4];
                int r0 = (8*kt + tg)*256;
                int r1 = (8*kt + 4 + tg)*256;
                #pragma unroll
                for (int i = 0; i < 6; i++) {
                    unsigned bh0 = bh[i][r0], bh1 = bh[i][r1];
                    unsigned bl0 = bh[i][4*32768 + r0], bl1 = bh[i][4*32768 + r1];
                    mma_bf16(acc[i], ah, bh0, bh1);
                    mma_bf16(acc[i], ah, bl0, bl1);
                    mma_bf16(acc[i], al, bh0, bh1);
                }
            }

            #pragma unroll
            for (int i = 0; i < 6; i++) {
                int nt = 6*wq4 + i;
                int sel = nt >> 3;
                int lcol = (nt & 7)*8 + 2*tg;
                const float* bias = (sel == 0) ? bq : (sel == 1) ? bk : bv;
                float bz0 = bias[h*64 + lcol], bz1 = bias[h*64 + lcol + 1];
                float c0 = acc[i][0] + bz0, c1 = acc[i][1] + bz1;
                float c2 = acc[i][2] + bz0, c3 = acc[i][3] + bz1;
                if (sel < 2) {
                    int plane = (sel == 0) ? QHI : KHI;
                    int uidx = lcol >> 1;
                    unsigned hi, lo;
                    split2(c0, c1, hi, lo);
                    smu[plane + rowA*36 + uidx] = hi;
                    smu[plane + 2304 + rowA*36 + uidx] = lo;
                    split2(c2, c3, hi, lo);
                    smu[plane + (rowA + 8)*36 + uidx] = hi;
                    smu[plane + 2304 + (rowA + 8)*36 + uidx] = lo;
                } else {
                    *(float2*)(VFf + rowA*66 + lcol) = make_float2(c0, c1);
                    *(float2*)(VFf + (rowA + 8)*66 + lcol) = make_float2(c2, c3);
                }
            }
        }
        __syncthreads();

        // ====== repack V (transpose) + scores ===
        for (int idx = t; idx < 2048; idx += 512) {
            int dim = idx >> 5, sh = idx & 31;
            float v0 = VFf[(2*sh)*66 + dim];
            float v1 = VFf[(2*sh + 1)*66 + dim];
            unsigned hi, lo;
            split2(v0, v1, hi, lo);
            smu[VHI + dim*36 + sh] = hi;
            smu[VLO + dim*36 + sh] = lo;
        }
        {
            float sacc[2][4];
            #pragma unroll
            for (int i = 0; i < 2; i++)
                #pragma unroll
                for (int j = 0; j < 4; j++) sacc[i][j] = 0.f;
            for (int kt = 0; kt < 4; kt++) {
                unsigned ah[4], al[4];
                int base = rowA*36 + 8*kt + tg;
                ah[0] = smu[QHI + base];       ah[1] = smu[QHI + base + 8*36];
                ah[2] = smu[QHI + base + 4];   ah[3] = smu[QHI + base + 8*36 + 4];
                al[0] = smu[QLO + base];       al[1] = smu[QLO + base + 8*36];
                al[2] = smu[QLO + base + 4];   al[3] = smu[QLO + base + 8*36 + 4];
                #pragma unroll
                for (int i = 0; i < 2; i++) {
                    int key = (2*wq4 + i)*8 + g;
                    int bb = key*36 + 8*kt + tg;
                    unsigned bh0 = smu[KHI + bb], bh1 = smu[KHI + bb + 4];
                    unsigned bl0 = smu[KLO + bb], bl1 = smu[KLO + bb + 4];
                    mma_bf16(sacc[i], ah, bh0, bh1);
                    mma_bf16(sacc[i], ah, bl0, bl1);
                    mma_bf16(sacc[i], al, bh0, bh1);
                }
            }
            #pragma unroll
            for (int i = 0; i < 2; i++) {
                int col = (2*wq4 + i)*8 + 2*tg;
                *(float2*)(SSf + rowA*66 + col) =
                    make_float2(sacc[i][0]*0.125f, sacc[i][1]*0.125f);
                *(float2*)(SSf + (rowA + 8)*66 + col) =
                    make_float2(sacc[i][2]*0.125f, sacc[i][3]*0.125f);
            }
        }
        __syncthreads();

        // ====== causal softmax ======
        {
            int row = t >> 3, sub = t & 7;
            float* Srow = SSf + row*66;
            float m = -3.402823466e38f;
            for (int j = sub; j <= row; j += 8) m = fmaxf(m, Srow[j]);
            m = fmaxf(m, __shfl_xor_sync(0xffffffffu, m, 1));
            m = fmaxf(m, __shfl_xor_sync(0xffffffffu, m, 2));
            m = fmaxf(m, __shfl_xor_sync(0xffffffffu, m, 4));
            float ssum = 0.f;
            for (int j = sub; j < 64; j += 8) {
                if (j <= row) {
                    float e = __expf(Srow[j] - m);
                    Srow[j] = e; ssum += e;
                } else Srow[j] = 0.f;
            }
            ssum += __shfl_xor_sync(0xffffffffu, ssum, 1);
            ssum += __shfl_xor_sync(0xffffffffu, ssum, 2);
            ssum += __shfl_xor_sync(0xffffffffu, ssum, 4);
            float inv = 1.f / ssum;
            for (int j = sub; j <= row; j += 8) Srow[j] *= inv;
        }
        __syncthreads();

        // ====== pack probs into S planes (alias Q planes) ======
        for (int idx = t; idx < 2048; idx += 512) {
            int r = idx >> 5, jh = idx & 31;
            float v0 = SSf[r*66 + 2*jh];
            float v1 = SSf[r*66 + 2*jh + 1];
            unsigned hi, lo;
            split2(v0, v1, hi, lo);
            smu[QHI + r*36 + jh] = hi;
            smu[QLO + r*36 + jh] = lo;
        }
        __syncthreads();

        // ====== H = S @ V ======
        {
            float hacc[2][4];
            #pragma unroll
            for (int i = 0; i < 2; i++)
                #pragma unroll
                for (int j = 0; j < 4; j++) hacc[i][j] = 0.f;
            for (int kt = 0; kt < 4; kt++) {
                unsigned ah[4], al[4];
                int base = rowA*36 + 8*kt + tg;
                ah[0] = smu[QHI + base];       ah[1] = smu[QHI + base + 8*36];
                ah[2] = smu[QHI + base + 4];   ah[3] = smu[QHI + base + 8*36 + 4];
                al[0] = smu[QLO + base];       al[1] = smu[QLO + base + 8*36];
                al[2] = smu[QLO + base + 4];   al[3] = smu[QLO + base + 8*36 + 4];
                #pragma unroll
                for (int i = 0; i < 2; i++) {
                    int dim = (2*wq4 + i)*8 + g;
                    int bb = dim*36 + 8*kt + tg;
                    unsigned bh0 = smu[VHI + bb], bh1 = smu[VHI + bb + 4];
                    unsigned bl0 = smu[VLO + bb], bl1 = smu[VLO + bb + 4];
                    mma_bf16(hacc[i], ah, bh0, bh1);
                    mma_bf16(hacc[i], ah, bl0, bl1);
                    mma_bf16(hacc[i], al, bh0, bh1);
                }
            }
            __syncthreads();
            #pragma unroll
            for (int i = 0; i < 2; i++) {
                int lcol = (2*wq4 + i)*8 + 2*tg;
                int uidx = lcol >> 1;
                unsigned hi, lo;
                split2(hacc[i][0], hacc[i][1], hi, lo);
                smu[KHI + rowA*36 + uidx] = hi;
                smu[KLO + rowA*36 + uidx] = lo;
                split2(hacc[i][2], hacc[i][3], hi, lo);
                smu[KHI + (rowA + 8)*36 + uidx] = hi;
                smu[KLO + (rowA + 8)*36 + uidx] = lo;
            }
        }
        __syncthreads();

        // ====== accumulate H @ Wo into oacc ======
        {
            for (int kt = 0; kt < 4; kt++) {
                unsigned ah[4], al[4];
                int base = rowA*36 + 8*kt + tg;
                ah[0] = smu[KHI + base];       ah[1] = smu[KHI + base + 8*36];
                ah[2] = smu[KHI + base + 4];   ah[3] = smu[KHI + base + 8*36 + 4];
                al[0] = smu[KLO + base];       al[1] = smu[KLO + base + 8*36];
                al[2] = smu[KLO + base + 4];   al[3] = smu[KLO + base + 8*36 + 4];
                int r0 = (h*32 + 8*kt + tg)*256;
                int r1 = (h*32 + 8*kt + 4 + tg)*256;
                #pragma unroll
                for (int i = 0; i < 8; i++) {
                    int ncol = wq4*64 + 8*i + g;
                    unsigned bh0 = pwo_hi[r0 + ncol], bh1 = pwo_hi[r1 + ncol];
                    unsigned bl0 = pwo_lo[r0 + ncol], bl1 = pwo_lo[r1 + ncol];
                    mma_bf16(oacc[i], ah, bh0, bh1);
                    mma_bf16(oacc[i], ah, bl0, bl1);
                    mma_bf16(oacc[i], al, bh0, bh1);
                }
            }
        }
        __syncthreads();
    }

    // ---- epilogue ----
    {
        const float* xg = g_xt + b*16384;
        float* dst = g_xattn + b*16384;
        #pragma unroll
        for (int i = 0; i < 8; i++) {
            int col = wq4*64 + 8*i + 2*tg;
            float b0 = bo[col], b1 = bo[col + 1];
            float2 rA = *(const float2*)(xg + rowA*256 + col);
            float2 rB = *(const float2*)(xg + (rowA + 8)*256 + col);
            *(float2*)(dst + rowA*256 + col) =
                make_float2(oacc[i][0] + b0 + rA.x, oacc[i][1] + b1 + rA.y);
            *(float2*)(dst + (rowA + 8)*256 + col) =
                make_float2(oacc[i][2] + b0 + rB.x, oacc[i][3] + b1 + rB.y);
        }
    }
}

// ---------------------------------------------------------------------------
// Kernel 5: scatter-max pooling
// ---------------------------------------------------------------------------
__global__ __launch_bounds__(256) void scatter_kernel() {
    int p = blockIdx.x, n = blockIdx.y, t = threadIdx.x;
    __shared__ unsigned char ids[64];
    if (t < 64) ids[t] = g_idx[(p*64 + n)*64 + t];
    __syncthreads();
    int c0 = 0, c1 = 0, c2 = 0, c3 = 0;
    #pragma unroll 8
    for (int s = 0; s < 64; s++) {
        int a = ids[s];
        c0 += (a == 0); c1 += (a == 1); c2 += (a == 2); c3 += (a == 3);
    }
    const float* src = g_xattn + (size_t)(n*16 + p)*16384 + t;
    float m0 = -3.402823466e38f, m1 = m0, m2 = m0, m3 = m0;
    #pragma unroll 8
    for (int s = 0; s < 64; s++) {
        float v = src[s*256];
        int a = ids[s];
        if (a == 0) m0 = fmaxf(m0, v);
        else if (a == 1) m1 = fmaxf(m1, v);
        else if (a == 2) m2 = fmaxf(m2, v);
        else m3 = fmaxf(m3, v);
    }
    if (c0 < 64) m0 = fmaxf(m0, 0.f);
    if (c1 < 64) m1 = fmaxf(m1, 0.f);
    if (c2 < 64) m2 = fmaxf(m2, 0.f);
    if (c3 < 64) m3 = fmaxf(m3, 0.f);
    float* dst = g_clustered + (size_t)(p*64 + n)*1024 + t;
    dst[0]   = m0;
    dst[256] = m1;
    dst[512] = m2;
    dst[768] = m3;
}

// ---------------------------------------------------------------------------
// Kernel 6: per-part FC
// ---------------------------------------------------------------------------
__global__ __launch_bounds__(256) void fc_kernel(const float* __restrict__ fcb,
                                                 float* __restrict__ out) {
    int p = blockIdx.x, n0 = blockIdx.y * 16, t = threadIdx.x;
    extern __shared__ float cl[];
    for (int nn = 0; nn < 16; nn++) {
        const float* src = g_clustered + (size_t)(p*64 + n0 + nn)*1024;
        for (int i = t; i < 1024; i += 256) cl[nn*1024 + i] = src[i];
    }
    __syncthreads();
    int o0 = t & 63, g = t >> 6;
    float acc[4][4];
    #pragma unroll
    for (int a = 0; a < 4; a++)
        #pragma unroll
        for (int bb = 0; bb < 4; bb++) acc[a][bb] = 0.f;
    const float* F = fcb + (size_t)p*1024*256 + o0;
    for (int kc = 0; kc < 1024; kc++) {
        float wv[4], cv[4];
        #pragma unroll
        for (int bb = 0; bb < 4; bb++) wv[bb] = F[(size_t)kc*256 + 64*bb];
        #pragma unroll
        for (int a = 0; a < 4; a++) cv[a] = cl[(g*4 + a)*1024 + kc];
        #pragma unroll
        for (int a = 0; a < 4; a++)
            #pragma unroll
            for (int bb = 0; bb < 4; bb++)
                acc[a][bb] = fmaf(cv[a], wv[bb], acc[a][bb]);
    }
    #pragma unroll
    for (int a = 0; a < 4; a++) {
        int n = n0 + g*4 + a;
        #pragma unroll
        for (int bb = 0; bb < 4; bb++) {
            int o = o0 + 64*bb;
            out[(size_t)n*4096 + o*16 + p] = acc[a][bb];
        }
    }
}

// ---------------------------------------------------------------------------
extern "C" void kernel_launch(void* const* d_in, const int* in_sizes, int n_in,
                              void* d_out, int out_size) {
    const float* x    = (const float*)d_in[0];
    const float* prot = (const float*)d_in[1];
    const float* Wq   = (const float*)d_in[2];
    const float* bq   = (const float*)d_in[3];
    const float* Wk   = (const float*)d_in[4];
    const float* bk   = (const float*)d_in[5];
    const float* Wv   = (const float*)d_in[6];
    const float* bv   = (const float*)d_in[7];
    const float* Wo   = (const float*)d_in[8];
    const float* bo   = (const float*)d_in[9];
    const float* fcb  = (const float*)d_in[10];
    float* out = (float*)d_out;

    cudaFuncSetAttribute(attn_kernel, cudaFuncAttributeMaxDynamicSharedMemorySize, SMEM_U32*4);
    cudaFuncSetAttribute(assign_kernel, cudaFuncAttributeMaxDynamicSharedMemorySize, 71680);
    cudaFuncSetAttribute(fc_kernel, cudaFuncAttributeMaxDynamicSharedMemorySize, 65536);

    packw_kernel<<<dim3(128, 4), 256>>>(Wq, Wk, Wv, Wo);
    transpose_kernel<<<NN*SS, 256>>>(x);
    protonorm_kernel<<<PP*KK, 256>>>(prot);
    assign_kernel<<<dim3(PP, NN), 256, 71680>>>();
    if (out_size >= NN*CC*PP + NN*SS)
        mode_kernel<<<16, 256>>>(out + NN*CC*PP);
    attn_kernel<<<NB, 512, SMEM_U32*4>>>(bq, bk, bv, bo);
    scatter_kernel<<<dim3(PP, NN), 256>>>();
    fc_kernel<<<dim3(PP, 4), 256, 65536>>>(fcb, out);
}